// round 9
// baseline (speedup 1.0000x reference)
#include <cuda_runtime.h>
#include <cuda_bf16.h>
#include <mma.h>
#include <cstdint>
#include <math.h>

using namespace nvcuda;

#define NN 20000
#define EE 160000
#define HIDD 128
#define NHEADS 8
#define NG 64

// ---------------- scratch (device globals; no allocation) ----------------
__device__ float g_h[NN * HIDD];
__device__ float g_q[NN * 1024];
__device__ float g_k[NN * 1024];
__device__ float g_v[NN * 1024];
__device__ float g_r[NN * HIDD];
__device__ float g_att[NN * HIDD];     // attention output (layers 0-2)
__device__ float g_attm[NN * HIDD];    // head-mean output for layer 3
__device__ float g_logit[EE * NHEADS];
__device__ float g_ex[EE * NHEADS];
__device__ float g_m[NN * NHEADS];
__device__ float g_den[NN * NHEADS];
__device__ double g_sum[HIDD];
__device__ double g_sq[HIDD];
__device__ float g_scale[HIDD];
__device__ float g_shift[HIDD];
__device__ float g_cnt[NG];
// bf16 split operands
__device__ __nv_bfloat16 g_ah[NN * HIDD];
__device__ __nv_bfloat16 g_al[NN * HIDD];
__device__ __nv_bfloat16 g_wth[1024 * 128];
__device__ __nv_bfloat16 g_wtl[1024 * 128];

// ============ tensor-core GEMM via wmma (portable HMMA path) ============
// C[M,KO] = A[M,128] @ W[128,KO] + bias, with A and Wt given as bf16 hi/lo splits.
// Wt is W transposed: Bt[KO,128] so both operands are k-contiguous.
// Block: 128x64 output tile, 256 threads = 8 warps (4x2), each warp 32x32
// (2x2 fragments of 16x16). 3 split products: Ah*Bh + Ah*Bl + Al*Bh.
#define PAD_LD 136  // 128 + 8 elements, multiple of 8 for wmma ldm
#define WG_SMEM ((128 + 128 + 64 + 64) * PAD_LD * 2)  // 104448 bytes

__global__ __launch_bounds__(256) void wgemm_k(
    const __nv_bfloat16* __restrict__ Ah, const __nv_bfloat16* __restrict__ Al,
    const __nv_bfloat16* __restrict__ Bh, const __nv_bfloat16* __restrict__ Bl,
    const float* __restrict__ bias, float* __restrict__ C, int M, int KO) {
    extern __shared__ char smem[];
    __nv_bfloat16* sAh = (__nv_bfloat16*)smem;       // 128 x PAD_LD
    __nv_bfloat16* sAl = sAh + 128 * PAD_LD;
    __nv_bfloat16* sBh = sAl + 128 * PAD_LD;          // 64 x PAD_LD
    __nv_bfloat16* sBl = sBh + 64 * PAD_LD;
    float* sC = (float*)smem;                          // reused after compute

    const int tid = threadIdx.x;
    const int row0 = blockIdx.x * 128;
    const int col0 = blockIdx.y * 64;

    // load A tiles (hi+lo), 8-elem (16B) chunks
    const uint4 z4 = make_uint4(0u, 0u, 0u, 0u);
    for (int c = tid; c < 2048; c += 256) {
        int r = c >> 4, c8 = c & 15;
        int gr = row0 + r;
        uint4 vh = z4, vl = z4;
        if (gr < M) {
            vh = *(const uint4*)(Ah + (size_t)gr * 128 + c8 * 8);
            vl = *(const uint4*)(Al + (size_t)gr * 128 + c8 * 8);
        }
        *(uint4*)(sAh + r * PAD_LD + c8 * 8) = vh;
        *(uint4*)(sAl + r * PAD_LD + c8 * 8) = vl;
    }
    // load B tiles (64 rows of Wt, always in range since KO % 64 == 0)
    for (int c = tid; c < 1024; c += 256) {
        int r = c >> 4, c8 = c & 15;
        int gr = col0 + r;
        *(uint4*)(sBh + r * PAD_LD + c8 * 8) = *(const uint4*)(Bh + (size_t)gr * 128 + c8 * 8);
        *(uint4*)(sBl + r * PAD_LD + c8 * 8) = *(const uint4*)(Bl + (size_t)gr * 128 + c8 * 8);
    }
    __syncthreads();

    const int wid = tid >> 5;
    const int wr = wid >> 1;   // 0..3  (m direction, 32 rows each)
    const int wc = wid & 1;    // 0..1  (n direction, 32 cols each)

    wmma::fragment<wmma::accumulator, 16, 16, 16, float> acc[2][2];
#pragma unroll
    for (int i = 0; i < 2; i++)
#pragma unroll
        for (int j = 0; j < 2; j++) wmma::fill_fragment(acc[i][j], 0.0f);

#pragma unroll
    for (int k0 = 0; k0 < 128; k0 += 16) {
        wmma::fragment<wmma::matrix_a, 16, 16, 16, __nv_bfloat16, wmma::row_major> fah[2], fal[2];
        wmma::fragment<wmma::matrix_b, 16, 16, 16, __nv_bfloat16, wmma::col_major> fbh[2], fbl[2];
#pragma unroll
        for (int i = 0; i < 2; i++) {
            wmma::load_matrix_sync(fah[i], sAh + (wr * 32 + i * 16) * PAD_LD + k0, PAD_LD);
            wmma::load_matrix_sync(fal[i], sAl + (wr * 32 + i * 16) * PAD_LD + k0, PAD_LD);
            wmma::load_matrix_sync(fbh[i], sBh + (wc * 32 + i * 16) * PAD_LD + k0, PAD_LD);
            wmma::load_matrix_sync(fbl[i], sBl + (wc * 32 + i * 16) * PAD_LD + k0, PAD_LD);
        }
#pragma unroll
        for (int i = 0; i < 2; i++)
#pragma unroll
            for (int j = 0; j < 2; j++) {
                wmma::mma_sync(acc[i][j], fah[i], fbh[j], acc[i][j]);
                wmma::mma_sync(acc[i][j], fah[i], fbl[j], acc[i][j]);
                wmma::mma_sync(acc[i][j], fal[i], fbh[j], acc[i][j]);
            }
    }
    __syncthreads();   // done reading operand smem; reuse as sC

#pragma unroll
    for (int i = 0; i < 2; i++)
#pragma unroll
        for (int j = 0; j < 2; j++)
            wmma::store_matrix_sync(sC + (wr * 32 + i * 16) * 64 + wc * 32 + j * 16,
                                    acc[i][j], 64, wmma::mem_row_major);
    __syncthreads();

    // epilogue: bias + vectorized global store (2048 float4 = 128x64)
    for (int c = tid; c < 2048; c += 256) {
        int r = c >> 4, q4 = c & 15;
        int gr = row0 + r;
        if (gr < M) {
            int gc = col0 + q4 * 4;
            float4 o = *(float4*)(sC + r * 64 + q4 * 4);
            o.x += bias[gc + 0];
            o.y += bias[gc + 1];
            o.z += bias[gc + 2];
            o.w += bias[gc + 3];
            *(float4*)(C + (size_t)gr * KO + gc) = o;
        }
    }
}

// ---------------- operand split kernels ----------------
__global__ void asplit_k(const float* __restrict__ a, __nv_bfloat16* __restrict__ hi,
                         __nv_bfloat16* __restrict__ lo, int n) {
    int i = blockIdx.x * blockDim.x + threadIdx.x;
    if (i >= n) return;
    float v = a[i];
    __nv_bfloat16 h = __float2bfloat16(v);
    hi[i] = h;
    lo[i] = __float2bfloat16(v - __bfloat162float(h));
}

// W [128, KO] fp32 -> Wt hi/lo [KO, 128] bf16 (tiled transpose)
__global__ void wsplit_k(const float* __restrict__ W, __nv_bfloat16* __restrict__ th,
                         __nv_bfloat16* __restrict__ tl, int KO) {
    __shared__ float t[32][33];
    int x = threadIdx.x, y = threadIdx.y; // 32 x 8
#pragma unroll
    for (int i = 0; i < 32; i += 8) {
        int k = blockIdx.y * 32 + y + i;   // W row
        int o = blockIdx.x * 32 + x;       // W col
        t[y + i][x] = W[(size_t)k * KO + o];
    }
    __syncthreads();
#pragma unroll
    for (int i = 0; i < 32; i += 8) {
        int o = blockIdx.x * 32 + y + i;   // out row (KO dim)
        int k = blockIdx.y * 32 + x;       // out col (128 dim)
        float v = t[x][y + i];
        __nv_bfloat16 h = __float2bfloat16(v);
        th[(size_t)o * 128 + k] = h;
        tl[(size_t)o * 128 + k] = __float2bfloat16(v - __bfloat162float(h));
    }
}

// ---------------- elementwise / fill ----------------
__global__ void fill_k(float* __restrict__ p, float v, int n) {
    int i = blockIdx.x * blockDim.x + threadIdx.x;
    if (i < n) p[i] = v;
}

// ---------------- segment softmax pieces ----------------
__device__ __forceinline__ void atomicMaxF(float* addr, float val) {
    int* ia = (int*)addr;
    int old = *ia;
    while (__int_as_float(old) < val) {
        int prev = atomicCAS(ia, old, __float_as_int(val));
        if (prev == old) break;
        old = prev;
    }
}

// fused logits + segment max (layers 0-2, per-head dim 16)
__global__ void edge_logits16max_k(const float* __restrict__ q, const float* __restrict__ k,
                                   const int* __restrict__ src, const int* __restrict__ dst,
                                   float* __restrict__ logit, float* __restrict__ m) {
    int idx = blockIdx.x * blockDim.x + threadIdx.x;
    if (idx >= EE * NHEADS) return;
    int e = idx >> 3, h = idx & 7;
    int de = dst[e];
    const float4* qp = (const float4*)(q + (size_t)de * 128 + h * 16);
    const float4* kp = (const float4*)(k + (size_t)src[e] * 128 + h * 16);
    float s = 0.f;
#pragma unroll
    for (int i = 0; i < 4; i++) {
        float4 a = qp[i], b = kp[i];
        s += a.x * b.x + a.y * b.y + a.z * b.z + a.w * b.w;
    }
    s *= 0.25f; // 1/sqrt(16)
    logit[idx] = s;
    atomicMaxF(&m[de * NHEADS + h], s);
}

// fused logits + segment max (layer 3, per-head dim 128)
__global__ void edge_logits128max_k(const float* __restrict__ q, const float* __restrict__ k,
                                    const int* __restrict__ src, const int* __restrict__ dst,
                                    float* __restrict__ logit, float* __restrict__ m) {
    int idx = blockIdx.x * blockDim.x + threadIdx.x;
    if (idx >= EE * NHEADS) return;
    int e = idx >> 3, h = idx & 7;
    int de = dst[e];
    const float4* qp = (const float4*)(q + (size_t)de * 1024 + h * 128);
    const float4* kp = (const float4*)(k + (size_t)src[e] * 1024 + h * 128);
    float s = 0.f;
#pragma unroll
    for (int i = 0; i < 32; i++) {
        float4 a = qp[i], b = kp[i];
        s += a.x * b.x + a.y * b.y + a.z * b.z + a.w * b.w;
    }
    s *= 0.08838834764831845f; // 1/sqrt(128)
    logit[idx] = s;
    atomicMaxF(&m[de * NHEADS + h], s);
}

__global__ void exp_denom_k(const float* __restrict__ logit, const int* __restrict__ dst,
                            const float* __restrict__ m, float* __restrict__ ex,
                            float* __restrict__ den) {
    int idx = blockIdx.x * blockDim.x + threadIdx.x;
    if (idx >= EE * NHEADS) return;
    int e = idx >> 3, h = idx & 7;
    float v = expf(logit[idx] - m[dst[e] * NHEADS + h]);
    ex[idx] = v;
    atomicAdd(&den[dst[e] * NHEADS + h], v);
}

// layers 0-2: out[dst, f] += a * v[src, f],  f in [0,128), head = f>>4
__global__ void scatter128_k(const float* __restrict__ ex, const float* __restrict__ den,
                             const float* __restrict__ v, const int* __restrict__ src,
                             const int* __restrict__ dst, float* __restrict__ out) {
    int e = blockIdx.x;
    int f = threadIdx.x;
    int de = dst[e], se = src[e];
    int h = f >> 4;
    float a = ex[e * NHEADS + h] / (den[de * NHEADS + h] + 1e-16f);
    atomicAdd(&out[(size_t)de * 128 + f], a * v[(size_t)se * 128 + f]);
}

// layer 3 with head-mean fused at edge level:
// out[dst, f] += (1/8) * sum_h a_eh * v[src, h*128 + f]   (128 atomics/edge, not 1024)
__global__ void scatter_mean1024_k(const float* __restrict__ ex, const float* __restrict__ den,
                                   const float* __restrict__ v, const int* __restrict__ src,
                                   const int* __restrict__ dst, float* __restrict__ out) {
    int e = blockIdx.x;
    int f = threadIdx.x; // 128
    int de = dst[e], se = src[e];
    __shared__ float a[NHEADS];
    if (f < NHEADS)
        a[f] = ex[e * NHEADS + f] / (den[de * NHEADS + f] + 1e-16f) * 0.125f;
    __syncthreads();
    const float* vp = v + (size_t)se * 1024 + f;
    float s = 0.f;
#pragma unroll
    for (int h = 0; h < NHEADS; h++) s += a[h] * vp[h * 128];
    atomicAdd(&out[(size_t)de * 128 + f], s);
}

// ---------------- beta gate ----------------
__global__ void beta_gate_k(const float* __restrict__ out, const float* __restrict__ r,
                            const float* __restrict__ Wb, float* __restrict__ hnew) {
    int node = blockIdx.x;
    int f = threadIdx.x; // 128
    float o = out[(size_t)node * 128 + f];
    float rr = r[(size_t)node * 128 + f];
    float p = o * Wb[f] + rr * Wb[128 + f] + (o - rr) * Wb[256 + f];
    __shared__ float sh[128];
    sh[f] = p;
    __syncthreads();
#pragma unroll
    for (int s = 64; s > 0; s >>= 1) {
        if (f < s) sh[f] += sh[f + s];
        __syncthreads();
    }
    float g = 1.f / (1.f + expf(-sh[0]));
    hnew[(size_t)node * 128 + f] = g * rr + (1.f - g) * o;
}

// ---------------- batch norm + relu ----------------
#define BN_ROWS 64
__global__ void bn_stats_k(const float* __restrict__ x, double* __restrict__ sum,
                           double* __restrict__ sq) {
    int f = threadIdx.x; // 128
    int r0 = blockIdx.x * BN_ROWS;
    float s = 0.f, s2 = 0.f;
    for (int i = 0; i < BN_ROWS; i++) {
        int r = r0 + i;
        if (r < NN) {
            float v = x[(size_t)r * 128 + f];
            s += v;
            s2 += v * v;
        }
    }
    atomicAdd(&sum[f], (double)s);
    atomicAdd(&sq[f], (double)s2);
}

__global__ void bn_finalize_k(const double* __restrict__ sum, const double* __restrict__ sq,
                              const float* __restrict__ gamma, const float* __restrict__ beta,
                              float* __restrict__ scale, float* __restrict__ shift) {
    int f = threadIdx.x;
    double mu = sum[f] / (double)NN;
    double var = sq[f] / (double)NN - mu * mu;
    float rs = (float)rsqrt(var + 1e-5);
    float sc = gamma[f] * rs;
    scale[f] = sc;
    shift[f] = beta[f] - (float)mu * sc;
}

// plain BN apply + relu (used after layer 3; no split needed)
__global__ void bn_apply_relu_k(float* __restrict__ x, const float* __restrict__ scale,
                                const float* __restrict__ shift) {
    int idx = blockIdx.x * blockDim.x + threadIdx.x;
    if (idx >= NN * 128) return;
    int f = idx & 127;
    float v = x[idx] * scale[f] + shift[f];
    x[idx] = v > 0.f ? v : 0.f;
}

// BN apply + relu + bf16 hi/lo split fused (feeds the next layer's GEMMs)
__global__ void bn_apply_relu_split_k(float* __restrict__ x, const float* __restrict__ scale,
                                      const float* __restrict__ shift,
                                      __nv_bfloat16* __restrict__ hi,
                                      __nv_bfloat16* __restrict__ lo) {
    int idx = blockIdx.x * blockDim.x + threadIdx.x;
    if (idx >= NN * 128) return;
    int f = idx & 127;
    float v = x[idx] * scale[f] + shift[f];
    v = v > 0.f ? v : 0.f;
    x[idx] = v;
    __nv_bfloat16 h = __float2bfloat16(v);
    hi[idx] = h;
    lo[idx] = __float2bfloat16(v - __bfloat162float(h));
}

// ---------------- pooling ----------------
__global__ void pool_sum_k(const float* __restrict__ h, const int* __restrict__ batch,
                           float* __restrict__ out, float* __restrict__ cnt) {
    int idx = blockIdx.x * blockDim.x + threadIdx.x;
    if (idx >= NN * 128) return;
    int n = idx >> 7, f = idx & 127;
    int b = batch[n];
    atomicAdd(&out[b * 128 + f], h[idx]);
    if (f == 0) atomicAdd(&cnt[b], 1.f);
}

__global__ void pool_div_k(float* __restrict__ out, const float* __restrict__ cnt) {
    int idx = blockIdx.x * blockDim.x + threadIdx.x;
    if (idx >= NG * 128) return;
    out[idx] /= fmaxf(cnt[idx >> 7], 1.f);
}

// ---------------- host-side launch helpers ----------------
static __nv_bfloat16 *s_ah, *s_al, *s_wth, *s_wtl;

static inline void run_wsplit(const float* W, int KO) {
    dim3 grid(KO / 32, 4), blk(32, 8);
    wsplit_k<<<grid, blk>>>(W, s_wth, s_wtl, KO);
}
static inline void run_gemm(const float* bias, float* C, int M, int KO) {
    dim3 grid((M + 127) / 128, KO / 64);
    wgemm_k<<<grid, 256, WG_SMEM>>>(s_ah, s_al, s_wth, s_wtl, bias, C, M, KO);
}

extern "C" void kernel_launch(void* const* d_in, const int* in_sizes, int n_in,
                              void* d_out, int out_size) {
    const float* x = (const float*)d_in[0];
    const int* ei = (const int*)d_in[1];
    const int* src = ei;
    const int* dst = ei + EE;
    const int* batch = (const int*)d_in[2];
    const float* Wp = (const float*)d_in[3];
    const float* bp = (const float*)d_in[4];
    const float* Wq = (const float*)d_in[5];
    const float* bq = (const float*)d_in[6];
    const float* Wk = (const float*)d_in[7];
    const float* bk = (const float*)d_in[8];
    const float* Wv = (const float*)d_in[9];
    const float* bv = (const float*)d_in[10];
    const float* Ws = (const float*)d_in[11];
    const float* bs = (const float*)d_in[12];
    const float* Wbeta = (const float*)d_in[13];
    const float* Wq3 = (const float*)d_in[14];
    const float* bq3 = (const float*)d_in[15];
    const float* Wk3 = (const float*)d_in[16];
    const float* bk3 = (const float*)d_in[17];
    const float* Wv3 = (const float*)d_in[18];
    const float* bv3 = (const float*)d_in[19];
    const float* Ws3 = (const float*)d_in[20];
    const float* bs3 = (const float*)d_in[21];
    const float* Wbeta3 = (const float*)d_in[22];
    const float* bn_gamma = (const float*)d_in[23];
    const float* bn_beta = (const float*)d_in[24];
    float* out = (float*)d_out;

    float *h, *q, *k, *v, *r, *att, *attm, *logit, *ex, *m, *den, *scale, *shift, *cnt;
    double *sum, *sq;
    cudaGetSymbolAddress((void**)&h, g_h);
    cudaGetSymbolAddress((void**)&q, g_q);
    cudaGetSymbolAddress((void**)&k, g_k);
    cudaGetSymbolAddress((void**)&v, g_v);
    cudaGetSymbolAddress((void**)&r, g_r);
    cudaGetSymbolAddress((void**)&att, g_att);
    cudaGetSymbolAddress((void**)&attm, g_attm);
    cudaGetSymbolAddress((void**)&logit, g_logit);
    cudaGetSymbolAddress((void**)&ex, g_ex);
    cudaGetSymbolAddress((void**)&m, g_m);
    cudaGetSymbolAddress((void**)&den, g_den);
    cudaGetSymbolAddress((void**)&scale, g_scale);
    cudaGetSymbolAddress((void**)&shift, g_shift);
    cudaGetSymbolAddress((void**)&cnt, g_cnt);
    cudaGetSymbolAddress((void**)&sum, g_sum);
    cudaGetSymbolAddress((void**)&sq, g_sq);
    cudaGetSymbolAddress((void**)&s_ah, g_ah);
    cudaGetSymbolAddress((void**)&s_al, g_al);
    cudaGetSymbolAddress((void**)&s_wth, g_wth);
    cudaGetSymbolAddress((void**)&s_wtl, g_wtl);

    cudaFuncSetAttribute(wgemm_k, cudaFuncAttributeMaxDynamicSharedMemorySize, WG_SMEM);

    const int EH = EE * NHEADS;
    const int eh_blocks = (EH + 255) / 256;
    const int nf_blocks = (NN * 128 + 255) / 256;
    const int bn_blocks = (NN + BN_ROWS - 1) / BN_ROWS;
    const int sp_blocks = (NN * 128 + 255) / 256;

    // prologue: h = x @ Wp + bp
    asplit_k<<<sp_blocks, 256>>>(x, s_ah, s_al, NN * 128);
    run_wsplit(Wp, 128);
    run_gemm(bp, h, NN, 128);
    asplit_k<<<sp_blocks, 256>>>(h, s_ah, s_al, NN * 128);

    for (int L = 0; L < 3; L++) {
        run_wsplit(Wq + (size_t)L * 128 * 128, 128);
        run_gemm(bq + L * 128, q, NN, 128);
        run_wsplit(Wk + (size_t)L * 128 * 128, 128);
        run_gemm(bk + L * 128, k, NN, 128);
        run_wsplit(Wv + (size_t)L * 128 * 128, 128);
        run_gemm(bv + L * 128, v, NN, 128);
        run_wsplit(Ws + (size_t)L * 128 * 128, 128);
        run_gemm(bs + L * 128, r, NN, 128);

        fill_k<<<(NN * NHEADS + 255) / 256, 256>>>(m, -1e30f, NN * NHEADS);
        cudaMemsetAsync(den, 0, NN * NHEADS * sizeof(float));
        cudaMemsetAsync(att, 0, (size_t)NN * 128 * sizeof(float));

        edge_logits16max_k<<<eh_blocks, 256>>>(q, k, src, dst, logit, m);
        exp_denom_k<<<eh_blocks, 256>>>(logit, dst, m, ex, den);
        scatter128_k<<<EE, 128>>>(ex, den, v, src, dst, att);
        beta_gate_k<<<NN, 128>>>(att, r, Wbeta + (size_t)L * 384, h);

        cudaMemsetAsync(sum, 0, HIDD * sizeof(double));
        cudaMemsetAsync(sq, 0, HIDD * sizeof(double));
        bn_stats_k<<<bn_blocks, 128>>>(h, sum, sq);
        bn_finalize_k<<<1, 128>>>(sum, sq, bn_gamma + L * 128, bn_beta + L * 128, scale, shift);
        // fused: BN apply + relu + bf16 split for the next layer's GEMMs
        bn_apply_relu_split_k<<<nf_blocks, 256>>>(h, scale, shift, s_ah, s_al);
    }

    // layer 3 (heads=8, per-head dim 128, concat=False -> head mean fused into scatter)
    run_wsplit(Wq3, 1024);
    run_gemm(bq3, q, NN, 1024);
    run_wsplit(Wk3, 1024);
    run_gemm(bk3, k, NN, 1024);
    run_wsplit(Wv3, 1024);
    run_gemm(bv3, v, NN, 1024);
    run_wsplit(Ws3, 128);
    run_gemm(bs3, r, NN, 128);

    fill_k<<<(NN * NHEADS + 255) / 256, 256>>>(m, -1e30f, NN * NHEADS);
    cudaMemsetAsync(den, 0, NN * NHEADS * sizeof(float));
    cudaMemsetAsync(attm, 0, (size_t)NN * 128 * sizeof(float));

    edge_logits128max_k<<<eh_blocks, 256>>>(q, k, src, dst, logit, m);
    exp_denom_k<<<eh_blocks, 256>>>(logit, dst, m, ex, den);
    scatter_mean1024_k<<<EE, 128>>>(ex, den, v, src, dst, attm);
    beta_gate_k<<<NN, 128>>>(attm, r, Wbeta3, h);

    cudaMemsetAsync(sum, 0, HIDD * sizeof(double));
    cudaMemsetAsync(sq, 0, HIDD * sizeof(double));
    bn_stats_k<<<bn_blocks, 128>>>(h, sum, sq);
    bn_finalize_k<<<1, 128>>>(sum, sq, bn_gamma + 3 * 128, bn_beta + 3 * 128, scale, shift);
    bn_apply_relu_k<<<nf_blocks, 256>>>(h, scale, shift);

    // global mean pool per graph
    cudaMemsetAsync(out, 0, NG * 128 * sizeof(float));
    cudaMemsetAsync(cnt, 0, NG * sizeof(float));
    pool_sum_k<<<nf_blocks, 256>>>(h, batch, out, cnt);
    pool_div_k<<<(NG * 128 + 255) / 256, 256>>>(out, cnt);
}

// round 12
// speedup vs baseline: 1.2685x; 1.2685x over previous
#include <cuda_runtime.h>
#include <math.h>

#define NN 20000
#define EE 160000
#define HIDD 128
#define NHEADS 8
#define NG 64

// ---------------- scratch (device globals; no allocation) ----------------
__device__ float g_h[NN * HIDD];
__device__ float g_q[NN * 1024];
__device__ float g_k[NN * 1024];
__device__ float g_v[NN * 1024];
__device__ float g_r[NN * HIDD];
__device__ float g_att[NN * HIDD];     // attention output (layers 0-2)
__device__ float g_attm[NN * HIDD];    // head-mean output for layer 3
__device__ float g_logit[EE * NHEADS];
__device__ float g_ex[EE * NHEADS];
__device__ float g_m[NN * NHEADS];
__device__ float g_den[NN * NHEADS];
__device__ double g_sum[HIDD];
__device__ double g_sq[HIDD];
__device__ float g_scale[HIDD];
__device__ float g_shift[HIDD];
__device__ float g_cnt[NG];

// ---------------- GEMM: C[M,KO] = A[M,128] @ W[128,KO] + bias -------------
// 64x64 tile, BK=32, double-buffered, 128 threads, 8x4 register tile.
// (proven in R6: 23.2us per 20000x128x128 launch, ~83% of fp32 SIMT floor)
__global__ __launch_bounds__(128) void gemm64_k(
    const float* __restrict__ A, const float* __restrict__ W,
    const float* __restrict__ bias, float* __restrict__ C, int M, int KO) {
    __shared__ float As[2][32][68];
    __shared__ float Ws[2][32][64];

    const int row0 = blockIdx.x * 64;
    const int col0 = blockIdx.y * 64;
    const int tid = threadIdx.x;
    const int tx = tid & 15, ty = tid >> 4;

    float acc[8][4];
#pragma unroll
    for (int i = 0; i < 8; i++)
#pragma unroll
        for (int j = 0; j < 4; j++) acc[i][j] = 0.f;

#pragma unroll
    for (int p = 0; p < 4; p++) {
        int t = tid + p * 128;
        int r = t >> 3, q4 = t & 7;
        int gr = row0 + r;
        float4 av = (gr < M) ? *(const float4*)(A + (size_t)gr * 128 + q4 * 4)
                             : make_float4(0.f, 0.f, 0.f, 0.f);
        As[0][q4 * 4 + 0][r] = av.x;
        As[0][q4 * 4 + 1][r] = av.y;
        As[0][q4 * 4 + 2][r] = av.z;
        As[0][q4 * 4 + 3][r] = av.w;
        int kk = t >> 4, n4 = t & 15;
        *(float4*)&Ws[0][kk][n4 * 4] =
            *(const float4*)(W + (size_t)kk * KO + col0 + n4 * 4);
    }
    __syncthreads();

    float4 aR[4], wR[4];
#pragma unroll
    for (int c = 0; c < 4; c++) {
        const int cur = c & 1;
        if (c < 3) {
            const int kcn = (c + 1) * 32;
#pragma unroll
            for (int p = 0; p < 4; p++) {
                int t = tid + p * 128;
                int r = t >> 3, q4 = t & 7;
                int gr = row0 + r;
                aR[p] = (gr < M)
                    ? *(const float4*)(A + (size_t)gr * 128 + kcn + q4 * 4)
                    : make_float4(0.f, 0.f, 0.f, 0.f);
                int kk = t >> 4, n4 = t & 15;
                wR[p] = *(const float4*)(W + (size_t)(kcn + kk) * KO + col0 + n4 * 4);
            }
        }
#pragma unroll
        for (int kk = 0; kk < 32; kk++) {
            float4 a0 = *(float4*)&As[cur][kk][ty * 8];
            float4 a1 = *(float4*)&As[cur][kk][ty * 8 + 4];
            float4 b  = *(float4*)&Ws[cur][kk][tx * 4];
            float av[8] = {a0.x, a0.y, a0.z, a0.w, a1.x, a1.y, a1.z, a1.w};
            float bv[4] = {b.x, b.y, b.z, b.w};
#pragma unroll
            for (int i = 0; i < 8; i++)
#pragma unroll
                for (int j = 0; j < 4; j++)
                    acc[i][j] = fmaf(av[i], bv[j], acc[i][j]);
        }
        if (c < 3) {
            const int nb = (c + 1) & 1;
#pragma unroll
            for (int p = 0; p < 4; p++) {
                int t = tid + p * 128;
                int r = t >> 3, q4 = t & 7;
                As[nb][q4 * 4 + 0][r] = aR[p].x;
                As[nb][q4 * 4 + 1][r] = aR[p].y;
                As[nb][q4 * 4 + 2][r] = aR[p].z;
                As[nb][q4 * 4 + 3][r] = aR[p].w;
                int kk = t >> 4, n4 = t & 15;
                *(float4*)&Ws[nb][kk][n4 * 4] = wR[p];
            }
        }
        __syncthreads();
    }

#pragma unroll
    for (int i = 0; i < 8; i++) {
        int gr = row0 + ty * 8 + i;
        if (gr < M) {
            int gc = col0 + tx * 4;
            float4 o;
            o.x = acc[i][0] + bias[gc + 0];
            o.y = acc[i][1] + bias[gc + 1];
            o.z = acc[i][2] + bias[gc + 2];
            o.w = acc[i][3] + bias[gc + 3];
            *(float4*)(C + (size_t)gr * KO + gc) = o;
        }
    }
}

// ---------------- elementwise / fill ----------------
__global__ void fill_k(float* __restrict__ p, float v, int n) {
    int i = blockIdx.x * blockDim.x + threadIdx.x;
    if (i < n) p[i] = v;
}

// ---------------- segment softmax pieces ----------------
__device__ __forceinline__ void atomicMaxF(float* addr, float val) {
    int* ia = (int*)addr;
    int old = *ia;
    while (__int_as_float(old) < val) {
        int prev = atomicCAS(ia, old, __float_as_int(val));
        if (prev == old) break;
        old = prev;
    }
}

// fused logits + segment max (layers 0-2, per-head dim 16)  [proven R9]
__global__ void edge_logits16max_k(const float* __restrict__ q, const float* __restrict__ k,
                                   const int* __restrict__ src, const int* __restrict__ dst,
                                   float* __restrict__ logit, float* __restrict__ m) {
    int idx = blockIdx.x * blockDim.x + threadIdx.x;
    if (idx >= EE * NHEADS) return;
    int e = idx >> 3, h = idx & 7;
    int de = dst[e];
    const float4* qp = (const float4*)(q + (size_t)de * 128 + h * 16);
    const float4* kp = (const float4*)(k + (size_t)src[e] * 128 + h * 16);
    float s = 0.f;
#pragma unroll
    for (int i = 0; i < 4; i++) {
        float4 a = qp[i], b = kp[i];
        s += a.x * b.x + a.y * b.y + a.z * b.z + a.w * b.w;
    }
    s *= 0.25f; // 1/sqrt(16)
    logit[idx] = s;
    atomicMaxF(&m[de * NHEADS + h], s);
}

// fused logits + segment max (layer 3, per-head dim 128), thread per (e,h)  [proven R9]
__global__ void edge_logits128max_k(const float* __restrict__ q, const float* __restrict__ k,
                                    const int* __restrict__ src, const int* __restrict__ dst,
                                    float* __restrict__ logit, float* __restrict__ m) {
    int idx = blockIdx.x * blockDim.x + threadIdx.x;
    if (idx >= EE * NHEADS) return;
    int e = idx >> 3, h = idx & 7;
    int de = dst[e];
    const float4* qp = (const float4*)(q + (size_t)de * 1024 + h * 128);
    const float4* kp = (const float4*)(k + (size_t)src[e] * 1024 + h * 128);
    float s = 0.f;
#pragma unroll
    for (int i = 0; i < 32; i++) {
        float4 a = qp[i], b = kp[i];
        s += a.x * b.x + a.y * b.y + a.z * b.z + a.w * b.w;
    }
    s *= 0.08838834764831845f; // 1/sqrt(128)
    logit[idx] = s;
    atomicMaxF(&m[de * NHEADS + h], s);
}

__global__ void exp_denom_k(const float* __restrict__ logit, const int* __restrict__ dst,
                            const float* __restrict__ m, float* __restrict__ ex,
                            float* __restrict__ den) {
    int idx = blockIdx.x * blockDim.x + threadIdx.x;
    if (idx >= EE * NHEADS) return;
    int e = idx >> 3, h = idx & 7;
    float v = expf(logit[idx] - m[dst[e] * NHEADS + h]);
    ex[idx] = v;
    atomicAdd(&den[dst[e] * NHEADS + h], v);
}

// layers 0-2: out[dst, f] += a * v[src, f],  f in [0,128), head = f>>4
__global__ void scatter128_k(const float* __restrict__ ex, const float* __restrict__ den,
                             const float* __restrict__ v, const int* __restrict__ src,
                             const int* __restrict__ dst, float* __restrict__ out) {
    int e = blockIdx.x;
    int f = threadIdx.x;
    int de = dst[e], se = src[e];
    int h = f >> 4;
    float a = ex[e * NHEADS + h] / (den[de * NHEADS + h] + 1e-16f);
    atomicAdd(&out[(size_t)de * 128 + f], a * v[(size_t)se * 128 + f]);
}

// layer 3 with head-mean fused at edge level  [proven R9]:
// out[dst, f] += (1/8) * sum_h a_eh * v[src, h*128 + f]   (128 atomics/edge, not 1024)
__global__ void scatter_mean1024_k(const float* __restrict__ ex, const float* __restrict__ den,
                                   const float* __restrict__ v, const int* __restrict__ src,
                                   const int* __restrict__ dst, float* __restrict__ out) {
    int e = blockIdx.x;
    int f = threadIdx.x; // 128
    int de = dst[e], se = src[e];
    __shared__ float a[NHEADS];
    if (f < NHEADS)
        a[f] = ex[e * NHEADS + f] / (den[de * NHEADS + f] + 1e-16f) * 0.125f;
    __syncthreads();
    const float* vp = v + (size_t)se * 1024 + f;
    float s = 0.f;
#pragma unroll
    for (int h = 0; h < NHEADS; h++) s += a[h] * vp[h * 128];
    atomicAdd(&out[(size_t)de * 128 + f], s);
}

// ---------------- beta gate ----------------
__global__ void beta_gate_k(const float* __restrict__ out, const float* __restrict__ r,
                            const float* __restrict__ Wb, float* __restrict__ hnew) {
    int node = blockIdx.x;
    int f = threadIdx.x; // 128
    float o = out[(size_t)node * 128 + f];
    float rr = r[(size_t)node * 128 + f];
    float p = o * Wb[f] + rr * Wb[128 + f] + (o - rr) * Wb[256 + f];
    __shared__ float sh[128];
    sh[f] = p;
    __syncthreads();
#pragma unroll
    for (int s = 64; s > 0; s >>= 1) {
        if (f < s) sh[f] += sh[f + s];
        __syncthreads();
    }
    float g = 1.f / (1.f + expf(-sh[0]));
    hnew[(size_t)node * 128 + f] = g * rr + (1.f - g) * o;
}

// ---------------- batch norm + relu ----------------
#define BN_ROWS 64
__global__ void bn_stats_k(const float* __restrict__ x, double* __restrict__ sum,
                           double* __restrict__ sq) {
    int f = threadIdx.x; // 128
    int r0 = blockIdx.x * BN_ROWS;
    float s = 0.f, s2 = 0.f;
    for (int i = 0; i < BN_ROWS; i++) {
        int r = r0 + i;
        if (r < NN) {
            float v = x[(size_t)r * 128 + f];
            s += v;
            s2 += v * v;
        }
    }
    atomicAdd(&sum[f], (double)s);
    atomicAdd(&sq[f], (double)s2);
}

__global__ void bn_finalize_k(const double* __restrict__ sum, const double* __restrict__ sq,
                              const float* __restrict__ gamma, const float* __restrict__ beta,
                              float* __restrict__ scale, float* __restrict__ shift) {
    int f = threadIdx.x;
    double mu = sum[f] / (double)NN;
    double var = sq[f] / (double)NN - mu * mu;
    float rs = (float)rsqrt(var + 1e-5);
    float sc = gamma[f] * rs;
    scale[f] = sc;
    shift[f] = beta[f] - (float)mu * sc;
}

__global__ void bn_apply_relu_k(float* __restrict__ x, const float* __restrict__ scale,
                                const float* __restrict__ shift) {
    int idx = blockIdx.x * blockDim.x + threadIdx.x;
    if (idx >= NN * 128) return;
    int f = idx & 127;
    float v = x[idx] * scale[f] + shift[f];
    x[idx] = v > 0.f ? v : 0.f;
}

// ---------------- pooling ----------------
__global__ void pool_sum_k(const float* __restrict__ h, const int* __restrict__ batch,
                           float* __restrict__ out, float* __restrict__ cnt) {
    int idx = blockIdx.x * blockDim.x + threadIdx.x;
    if (idx >= NN * 128) return;
    int n = idx >> 7, f = idx & 127;
    int b = batch[n];
    atomicAdd(&out[b * 128 + f], h[idx]);
    if (f == 0) atomicAdd(&cnt[b], 1.f);
}

__global__ void pool_div_k(float* __restrict__ out, const float* __restrict__ cnt) {
    int idx = blockIdx.x * blockDim.x + threadIdx.x;
    if (idx >= NG * 128) return;
    out[idx] /= fmaxf(cnt[idx >> 7], 1.f);
}

// ---------------- launch ----------------
static inline void run_gemm(const float* A, const float* W, const float* b, float* C,
                            int M, int KO) {
    dim3 grid((M + 63) / 64, KO / 64);
    gemm64_k<<<grid, 128>>>(A, W, b, C, M, KO);
}

extern "C" void kernel_launch(void* const* d_in, const int* in_sizes, int n_in,
                              void* d_out, int out_size) {
    const float* x = (const float*)d_in[0];
    const int* ei = (const int*)d_in[1];
    const int* src = ei;
    const int* dst = ei + EE;
    const int* batch = (const int*)d_in[2];
    const float* Wp = (const float*)d_in[3];
    const float* bp = (const float*)d_in[4];
    const float* Wq = (const float*)d_in[5];
    const float* bq = (const float*)d_in[6];
    const float* Wk = (const float*)d_in[7];
    const float* bk = (const float*)d_in[8];
    const float* Wv = (const float*)d_in[9];
    const float* bv = (const float*)d_in[10];
    const float* Ws = (const float*)d_in[11];
    const float* bs = (const float*)d_in[12];
    const float* Wbeta = (const float*)d_in[13];
    const float* Wq3 = (const float*)d_in[14];
    const float* bq3 = (const float*)d_in[15];
    const float* Wk3 = (const float*)d_in[16];
    const float* bk3 = (const float*)d_in[17];
    const float* Wv3 = (const float*)d_in[18];
    const float* bv3 = (const float*)d_in[19];
    const float* Ws3 = (const float*)d_in[20];
    const float* bs3 = (const float*)d_in[21];
    const float* Wbeta3 = (const float*)d_in[22];
    const float* bn_gamma = (const float*)d_in[23];
    const float* bn_beta = (const float*)d_in[24];
    float* out = (float*)d_out;

    float *h, *q, *k, *v, *r, *att, *attm, *logit, *ex, *m, *den, *scale, *shift, *cnt;
    double *sum, *sq;
    cudaGetSymbolAddress((void**)&h, g_h);
    cudaGetSymbolAddress((void**)&q, g_q);
    cudaGetSymbolAddress((void**)&k, g_k);
    cudaGetSymbolAddress((void**)&v, g_v);
    cudaGetSymbolAddress((void**)&r, g_r);
    cudaGetSymbolAddress((void**)&att, g_att);
    cudaGetSymbolAddress((void**)&attm, g_attm);
    cudaGetSymbolAddress((void**)&logit, g_logit);
    cudaGetSymbolAddress((void**)&ex, g_ex);
    cudaGetSymbolAddress((void**)&m, g_m);
    cudaGetSymbolAddress((void**)&den, g_den);
    cudaGetSymbolAddress((void**)&scale, g_scale);
    cudaGetSymbolAddress((void**)&shift, g_shift);
    cudaGetSymbolAddress((void**)&cnt, g_cnt);
    cudaGetSymbolAddress((void**)&sum, g_sum);
    cudaGetSymbolAddress((void**)&sq, g_sq);

    const int EH = EE * NHEADS;
    const int eh_blocks = (EH + 255) / 256;
    const int nf_blocks = (NN * 128 + 255) / 256;
    const int bn_blocks = (NN + BN_ROWS - 1) / BN_ROWS;

    // prologue: h = x @ Wp + bp
    run_gemm(x, Wp, bp, h, NN, 128);

    for (int L = 0; L < 3; L++) {
        run_gemm(h, Wq + (size_t)L * 128 * 128, bq + L * 128, q, NN, 128);
        run_gemm(h, Wk + (size_t)L * 128 * 128, bk + L * 128, k, NN, 128);
        run_gemm(h, Wv + (size_t)L * 128 * 128, bv + L * 128, v, NN, 128);
        run_gemm(h, Ws + (size_t)L * 128 * 128, bs + L * 128, r, NN, 128);

        fill_k<<<(NN * NHEADS + 255) / 256, 256>>>(m, -1e30f, NN * NHEADS);
        cudaMemsetAsync(den, 0, NN * NHEADS * sizeof(float));
        cudaMemsetAsync(att, 0, (size_t)NN * 128 * sizeof(float));

        edge_logits16max_k<<<eh_blocks, 256>>>(q, k, src, dst, logit, m);
        exp_denom_k<<<eh_blocks, 256>>>(logit, dst, m, ex, den);
        scatter128_k<<<EE, 128>>>(ex, den, v, src, dst, att);
        beta_gate_k<<<NN, 128>>>(att, r, Wbeta + (size_t)L * 384, h);

        cudaMemsetAsync(sum, 0, HIDD * sizeof(double));
        cudaMemsetAsync(sq, 0, HIDD * sizeof(double));
        bn_stats_k<<<bn_blocks, 128>>>(h, sum, sq);
        bn_finalize_k<<<1, 128>>>(sum, sq, bn_gamma + L * 128, bn_beta + L * 128, scale, shift);
        bn_apply_relu_k<<<nf_blocks, 256>>>(h, scale, shift);
    }

    // layer 3 (heads=8, per-head dim 128, concat=False -> head mean fused into scatter)
    run_gemm(h, Wq3, bq3, q, NN, 1024);
    run_gemm(h, Wk3, bk3, k, NN, 1024);
    run_gemm(h, Wv3, bv3, v, NN, 1024);
    run_gemm(h, Ws3, bs3, r, NN, 128);

    fill_k<<<(NN * NHEADS + 255) / 256, 256>>>(m, -1e30f, NN * NHEADS);
    cudaMemsetAsync(den, 0, NN * NHEADS * sizeof(float));
    cudaMemsetAsync(attm, 0, (size_t)NN * 128 * sizeof(float));

    edge_logits128max_k<<<eh_blocks, 256>>>(q, k, src, dst, logit, m);
    exp_denom_k<<<eh_blocks, 256>>>(logit, dst, m, ex, den);
    scatter_mean1024_k<<<EE, 128>>>(ex, den, v, src, dst, attm);
    beta_gate_k<<<NN, 128>>>(attm, r, Wbeta3, h);

    cudaMemsetAsync(sum, 0, HIDD * sizeof(double));
    cudaMemsetAsync(sq, 0, HIDD * sizeof(double));
    bn_stats_k<<<bn_blocks, 128>>>(h, sum, sq);
    bn_finalize_k<<<1, 128>>>(sum, sq, bn_gamma + 3 * 128, bn_beta + 3 * 128, scale, shift);
    bn_apply_relu_k<<<nf_blocks, 256>>>(h, scale, shift);

    // global mean pool per graph
    cudaMemsetAsync(out, 0, NG * 128 * sizeof(float));
    cudaMemsetAsync(cnt, 0, NG * sizeof(float));
    pool_sum_k<<<nf_blocks, 256>>>(h, batch, out, cnt);
    pool_div_k<<<(NG * 128 + 255) / 256, 256>>>(out, cnt);
}